// round 4
// baseline (speedup 1.0000x reference)
#include <cuda_runtime.h>
#include <cstdint>

namespace {
constexpr int EMBD  = 64;
constexpr int HID   = 128;
constexpr int NN    = 4096;
constexpr int P1    = 2047;
constexpr int STEPS = 4094;
constexpr int CS    = 8;
constexpr int TPB   = 256;
constexpr int NBT   = NN / TPB;     // 16 neighbors per thread
}

__device__ float g_xih[(size_t)P1 * 512];   // precomputed x@W_ih (permuted)
__device__ float g_hist[(size_t)P1 * HID];  // phase-1 h history

// ---------------- PTX helpers ----------------
__device__ __forceinline__ unsigned ctarank() {
    unsigned r; asm("mov.u32 %0, %%cluster_ctarank;" : "=r"(r)); return r;
}
__device__ __forceinline__ void cluster_sync_() {
    asm volatile("barrier.cluster.arrive.aligned;" ::: "memory");
    asm volatile("barrier.cluster.wait.aligned;" ::: "memory");
}
__device__ __forceinline__ unsigned mapa_(unsigned la, unsigned rank) {
    unsigned ra;
    asm("mapa.shared::cluster.u32 %0, %1, %2;" : "=r"(ra) : "r"(la), "r"(rank));
    return ra;
}
__device__ __forceinline__ void mbar_init(unsigned a, unsigned cnt) {
    asm volatile("mbarrier.init.shared.b64 [%0], %1;" :: "r"(a), "r"(cnt) : "memory");
}
__device__ __forceinline__ void mbar_expect(unsigned a, unsigned bytes) {
    asm volatile("mbarrier.arrive.expect_tx.shared.b64 _, [%0], %1;"
                 :: "r"(a), "r"(bytes) : "memory");
}
__device__ __forceinline__ void mbar_wait(unsigned a, unsigned parity) {
    asm volatile(
        "{\n\t.reg .pred P;\n"
        "WL%=:\n\t"
        "mbarrier.try_wait.parity.acquire.cluster.shared::cta.b64 P, [%0], %1, 0x989680;\n\t"
        "@P bra WD%=;\n\t"
        "bra WL%=;\n"
        "WD%=:\n\t}"
        :: "r"(a), "r"(parity) : "memory");
}
__device__ __forceinline__ void st_async_f32(unsigned raddr, float v, unsigned rmbar) {
    asm volatile(
        "st.async.shared::cluster.mbarrier::complete_tx::bytes.b32 [%0], %1, [%2];"
        :: "r"(raddr), "r"(__float_as_uint(v)), "r"(rmbar) : "memory");
}

// fast activations via MUFU (rel err ~1e-6, safe vs 1e-3 threshold)
__device__ __forceinline__ float fsig(float x) {
    return __fdividef(1.0f, 1.0f + __expf(-x));
}
__device__ __forceinline__ float ftanh(float x) {
    return __fdividef(2.0f, 1.0f + __expf(-2.0f * x)) - 1.0f;
}

// occupancy test for one neighbor: exact JAX linspace edge semantics
__device__ __forceinline__ void occ_point(float x, float y, float cx, float cy,
                                          unsigned& lo, unsigned& hi) {
    if (fabsf(x - cx) < 1.6f && fabsf(y - cy) < 1.6f) {
        int ix = -1, iy = -1;
#pragma unroll
        for (int c = 0; c < 6; c++) {
            float ex0 = cx + (0.5f * c - 1.5f);
            float ex1 = cx + (0.5f * c - 1.0f);
            if (x > ex0 && x < ex1) ix = c;
            float ey0 = cy + (0.5f * c - 1.5f);
            float ey1 = cy + (0.5f * c - 1.0f);
            if (y > ey0 && y < ey1) iy = c;
        }
        if (ix >= 0 && iy >= 0) {
            int b = ix * 6 + iy;
            if (b < 32) lo |= 1u << b; else hi |= 1u << (b - 32);
        }
    }
}

// ---------------- Kernel A: phase-1 precompute (fully parallel) ----------------
__global__ void __launch_bounds__(TPB) olstm_pre(
    const float* __restrict__ observed, const float* __restrict__ other,
    const float* __restrict__ W_emb, const float* __restrict__ b_emb,
    const float* __restrict__ W_ih)
{
    __shared__ __align__(16) float x100[100];
    __shared__ unsigned wlo[8], whi[8];
    const int t = blockIdx.x;
    const int tid = threadIdx.x;
    const float px = observed[t * 2],       py = observed[t * 2 + 1];
    const float cx = observed[(t + 1) * 2], cy = observed[(t + 1) * 2 + 1];
    const float dx = cx - px, dy = cy - py;

    const float2* oth2 = reinterpret_cast<const float2*>(other);
    unsigned lo = 0u, hi = 0u;
    for (int i = 0; i < NBT; i++) {
        float2 p = oth2[(size_t)(t + 1) * NN + i * TPB + tid];
        occ_point(p.x, p.y, cx, cy, lo, hi);
    }
    lo = __reduce_or_sync(0xffffffffu, lo);
    hi = __reduce_or_sync(0xffffffffu, hi);
    if ((tid & 31) == 0) { wlo[tid >> 5] = lo; whi[tid >> 5] = hi; }
    if (tid < EMBD) {
        float e = fmaf(dx, W_emb[tid * 2], fmaf(dy, W_emb[tid * 2 + 1], b_emb[tid]));
        x100[tid] = e > 0.0f ? e : 0.0f;
    }
    __syncthreads();
    if (tid >= 64 && tid < 100) {
        int b = tid - 64;
        unsigned fm = (b < 32)
            ? (wlo[0]|wlo[1]|wlo[2]|wlo[3]|wlo[4]|wlo[5]|wlo[6]|wlo[7])
            : (whi[0]|whi[1]|whi[2]|whi[3]|whi[4]|whi[5]|whi[6]|whi[7]);
        x100[tid] = ((fm >> (b & 31)) & 1u) ? 1.0f : 0.0f;
    }
    __syncthreads();

    const float4* xq = reinterpret_cast<const float4*>(x100);
    const float4* w0 = reinterpret_cast<const float4*>(W_ih + (size_t)tid * 100);
    const float4* w1 = reinterpret_cast<const float4*>(W_ih + (size_t)(tid + 256) * 100);
    float a0 = 0.0f, a1 = 0.0f;
#pragma unroll
    for (int i = 0; i < 25; i++) {
        float4 xx = xq[i], wa = w0[i], wb = w1[i];
        a0 = fmaf(wa.x, xx.x, a0); a0 = fmaf(wa.y, xx.y, a0);
        a0 = fmaf(wa.z, xx.z, a0); a0 = fmaf(wa.w, xx.w, a0);
        a1 = fmaf(wb.x, xx.x, a1); a1 = fmaf(wb.y, xx.y, a1);
        a1 = fmaf(wb.z, xx.z, a1); a1 = fmaf(wb.w, xx.w, a1);
    }
    // permute: idx = rk*64 + q*16 + jj for gate row gr = q*128 + rk*16 + jj
    const int r0 = tid, r1 = tid + 256;
    g_xih[(size_t)t * 512 + ((r0 >> 4) & 7) * 64 + (r0 >> 7) * 16 + (r0 & 15)] = a0;
    g_xih[(size_t)t * 512 + ((r1 >> 4) & 7) * 64 + (r1 >> 7) * 16 + (r1 & 15)] = a1;
}

// ---------------- Kernel B: sequential cluster (8 CTA x 256) ----------------
__global__ void __cluster_dims__(CS, 1, 1) __launch_bounds__(TPB, 1)
olstm_seq(const float* __restrict__ observed, const float* __restrict__ other,
          const float* __restrict__ W_emb, const float* __restrict__ b_emb,
          const float* __restrict__ W_ih,  const float* __restrict__ b_ih,
          const float* __restrict__ W_hh,  const float* __restrict__ b_hh,
          const float* __restrict__ W_out, const float* __restrict__ b_out,
          float* __restrict__ out)
{
    __shared__ __align__(16) float hbuf[2][HID];
    __shared__ __align__(16) float pcs[4];           // {pcx, pcy, dx, dy}
    __shared__ __align__(16) float Wocc[36 * 64];    // [bit][localrow]
    __shared__ unsigned wlo[8], whi[8];
    __shared__ __align__(8) unsigned long long mbar_s[2];

    const int tid  = threadIdx.x;
    const unsigned lane = tid & 31;
    const int warp = tid >> 5;
    const unsigned rk = ctarank();
    // thread = jj*16 + q*4 + p
    const int jj = tid >> 4;
    const int q  = (tid >> 2) & 3;
    const int p  = tid & 3;
    const int gr = q * HID + (int)rk * 16 + jj;      // global gate row

    // register-resident weights: 16 emb cols + 32 h cols (K-slice p)
    float w[48];
#pragma unroll
    for (int i = 0; i < 16; i++) w[i] = W_ih[(size_t)gr * 100 + p * 16 + i];
#pragma unroll
    for (int i = 0; i < 32; i++) w[16 + i] = W_hh[(size_t)gr * 128 + p * 32 + i];
    const float bs = b_ih[gr] + b_hh[gr];

    // per-thread embedding weights for its 16 emb cols
    float we0[16], we1[16], be[16];
#pragma unroll
    for (int i = 0; i < 16; i++) {
        int col = p * 16 + i;
        we0[i] = W_emb[col * 2]; we1[i] = W_emb[col * 2 + 1]; be[i] = b_emb[col];
    }

    // occupancy weight columns (sparse lookup by p==3 threads)
    for (int idx = tid; idx < 36 * 64; idx += TPB) {
        int b = idx >> 6, r = idx & 63;
        int g2 = (r >> 4) * HID + (int)rk * 16 + (r & 15);
        Wocc[idx] = W_ih[(size_t)g2 * 100 + 64 + b];
    }

    // head weights: warp0 rows 0,1 ; warp1 rows 2,3,4
    float woA[4] = {0,0,0,0}, woB[4] = {0,0,0,0}, woC[4] = {0,0,0,0};
    if (warp == 0) {
#pragma unroll
        for (int i = 0; i < 4; i++) {
            woA[i] = W_out[lane + 32 * i];
            woB[i] = W_out[HID + lane + 32 * i];
        }
    } else if (warp == 1) {
#pragma unroll
        for (int i = 0; i < 4; i++) {
            woA[i] = W_out[2 * HID + lane + 32 * i];
            woB[i] = W_out[3 * HID + lane + 32 * i];
            woC[i] = W_out[4 * HID + lane + 32 * i];
        }
    }
    const float bo0 = b_out[0], bo1 = b_out[1], bo2 = b_out[2],
                bo3 = b_out[3], bo4 = b_out[4];

    for (int i = tid; i < HID; i += TPB) { hbuf[0][i] = 0.0f; hbuf[1][i] = 0.0f; }

    const unsigned mb0  = (unsigned)__cvta_generic_to_shared(&mbar_s[0]);
    const unsigned mb1  = mb0 + 8;
    const unsigned la_h = (unsigned)__cvta_generic_to_shared(&hbuf[0][0]);
    if (tid == 0) { mbar_init(mb0, 1); mbar_init(mb1, 1); mbar_expect(mb0, 512); }
    __syncthreads();
    cluster_sync_();

    const float2* oth2 = reinterpret_cast<const float2*>(other);
    float2 nb[NBT];
    float cst = 0.0f;                       // cell state (sender lanes)
    float pcx = 0.0f, pcy = 0.0f, ppx = 0.0f, ppy = 0.0f;  // lane0/warp0 only
    const bool sender = (tid & 15) == 0;
    float xcur = (p == 0) ? g_xih[(size_t)rk * 64 + q * 16 + jj] : 0.0f;
    float xnext = 0.0f;

    // ======================= phase 1 (no __syncthreads) =======================
    for (int t = 0; t < P1; t++) {
        const int cur = t & 1, nxt = cur ^ 1;
        const unsigned mb_c = (t & 1) ? mb1 : mb0;
        const unsigned mb_n = (t & 1) ? mb0 : mb1;
        if (tid == 0) mbar_expect(mb_n, 512);

        // GEMV over h (32 cols per thread, 4 accumulators)
        const float4* hq = reinterpret_cast<const float4*>(hbuf[cur] + p * 32);
        float a0 = xcur, a1 = 0.0f, a2 = 0.0f, a3 = 0.0f;
#pragma unroll
        for (int i = 0; i < 8; i++) {
            float4 hh = hq[i];
            a0 = fmaf(w[16 + 4 * i], hh.x, a0); a1 = fmaf(w[17 + 4 * i], hh.y, a1);
            a2 = fmaf(w[18 + 4 * i], hh.z, a2); a3 = fmaf(w[19 + 4 * i], hh.w, a3);
        }
        float v = (a0 + a1) + (a2 + a3);
        v += __shfl_down_sync(0xffffffffu, v, 1);
        v += __shfl_down_sync(0xffffffffu, v, 2);
        v += bs;
        float av = (q == 2) ? ftanh(v) : fsig(v);
        float gi = av;
        float gf = __shfl_sync(0xffffffffu, av, (lane & 16u) | 4u);
        float gg = __shfl_sync(0xffffffffu, av, (lane & 16u) | 8u);
        float go = __shfl_sync(0xffffffffu, av, (lane & 16u) | 12u);
        float cN = fmaf(gf, cst, gi * gg);
        float hN = go * ftanh(cN);
        if (sender) {
            cst = cN;
            unsigned dst = la_h + (unsigned)((nxt * HID + (int)rk * 16 + jj) * 4);
#pragma unroll
            for (int r = 0; r < CS; r++)
                st_async_f32(mapa_(dst, (unsigned)r), hN, mapa_(mb_c, (unsigned)r));
            g_hist[(size_t)t * HID + rk * 16 + jj] = hN;   // off critical path
        }
        if (p == 0 && t + 1 < P1)
            xnext = g_xih[(size_t)(t + 1) * 512 + rk * 64 + q * 16 + jj];
        if (t == P1 - 1) {
#pragma unroll
            for (int i = 0; i < NBT; i++)
                nb[i] = oth2[(size_t)(P1 + 1) * NN + i * TPB + tid];
        }
        mbar_wait(mb_c, (t >> 1) & 1);
        // last two steps: compute positions for the phase-2 carry
        if (t >= P1 - 2 && warp == 0) {
            float u0 = 0.0f, u1 = 0.0f;
#pragma unroll
            for (int i = 0; i < 4; i++) {
                float hv = hbuf[nxt][lane + 32 * i];
                u0 = fmaf(hv, woA[i], u0); u1 = fmaf(hv, woB[i], u1);
            }
#pragma unroll
            for (int off = 16; off > 0; off >>= 1) {
                u0 += __shfl_xor_sync(0xffffffffu, u0, off);
                u1 += __shfl_xor_sync(0xffffffffu, u1, off);
            }
            if (lane == 0) {
                ppx = pcx; ppy = pcy;
                pcx = observed[(t + 1) * 2]     + u0 + bo0;
                pcy = observed[(t + 1) * 2 + 1] + u1 + bo1;
            }
        }
        xcur = xnext;
    }

    if (tid == 0) {
        pcs[0] = pcx; pcs[1] = pcy; pcs[2] = pcx - ppx; pcs[3] = pcy - ppy;
    }
    __syncthreads();

    // ======================= phase 2 (feedback) =======================
    for (int t = P1; t < STEPS; t++) {
        const int cur = t & 1, nxt = cur ^ 1;
        const unsigned mb_c = (t & 1) ? mb1 : mb0;
        const unsigned mb_n = (t & 1) ? mb0 : mb1;
        if (tid == 0) mbar_expect(mb_n, 512);

        const float cx = pcs[0], cy = pcs[1], dx = pcs[2], dy = pcs[3];

        // occupancy scan on prefetched neighbors
        unsigned lo = 0u, hi = 0u;
#pragma unroll
        for (int i = 0; i < NBT; i++) occ_point(nb[i].x, nb[i].y, cx, cy, lo, hi);
        lo = __reduce_or_sync(0xffffffffu, lo);
        hi = __reduce_or_sync(0xffffffffu, hi);
        if (lane == 0) { wlo[warp] = lo; whi[warp] = hi; }

        // GEMV: h part + per-thread embedding part
        const float4* hq = reinterpret_cast<const float4*>(hbuf[cur] + p * 32);
        float a0 = 0.0f, a1 = 0.0f, a2 = 0.0f, a3 = 0.0f;
#pragma unroll
        for (int i = 0; i < 8; i++) {
            float4 hh = hq[i];
            a0 = fmaf(w[16 + 4 * i], hh.x, a0); a1 = fmaf(w[17 + 4 * i], hh.y, a1);
            a2 = fmaf(w[18 + 4 * i], hh.z, a2); a3 = fmaf(w[19 + 4 * i], hh.w, a3);
        }
#pragma unroll
        for (int i = 0; i < 4; i++) {
            float e0 = fmaf(dx, we0[4*i+0], fmaf(dy, we1[4*i+0], be[4*i+0])); e0 = e0 > 0.0f ? e0 : 0.0f;
            float e1 = fmaf(dx, we0[4*i+1], fmaf(dy, we1[4*i+1], be[4*i+1])); e1 = e1 > 0.0f ? e1 : 0.0f;
            float e2 = fmaf(dx, we0[4*i+2], fmaf(dy, we1[4*i+2], be[4*i+2])); e2 = e2 > 0.0f ? e2 : 0.0f;
            float e3 = fmaf(dx, we0[4*i+3], fmaf(dy, we1[4*i+3], be[4*i+3])); e3 = e3 > 0.0f ? e3 : 0.0f;
            a0 = fmaf(w[4*i+0], e0, a0); a1 = fmaf(w[4*i+1], e1, a1);
            a2 = fmaf(w[4*i+2], e2, a2); a3 = fmaf(w[4*i+3], e3, a3);
        }
        __syncthreads();                                   // wlo/whi visibility
        if (p == 3) {
            unsigned flo = wlo[0]|wlo[1]|wlo[2]|wlo[3]|wlo[4]|wlo[5]|wlo[6]|wlo[7];
            unsigned fhi = whi[0]|whi[1]|whi[2]|whi[3]|whi[4]|whi[5]|whi[6]|whi[7];
            const int r = q * 16 + jj;
            while (flo) { int b = __ffs(flo) - 1; flo &= flo - 1; a0 += Wocc[b * 64 + r]; }
            while (fhi) { int b = __ffs(fhi) - 1; fhi &= fhi - 1; a0 += Wocc[(b + 32) * 64 + r]; }
        }
        if (t + 1 < STEPS) {                               // prefetch next neighbors
#pragma unroll
            for (int i = 0; i < NBT; i++)
                nb[i] = oth2[(size_t)(t + 2) * NN + i * TPB + tid];
        }

        float v = (a0 + a1) + (a2 + a3);
        v += __shfl_down_sync(0xffffffffu, v, 1);
        v += __shfl_down_sync(0xffffffffu, v, 2);
        v += bs;
        float av = (q == 2) ? ftanh(v) : fsig(v);
        float gi = av;
        float gf = __shfl_sync(0xffffffffu, av, (lane & 16u) | 4u);
        float gg = __shfl_sync(0xffffffffu, av, (lane & 16u) | 8u);
        float go = __shfl_sync(0xffffffffu, av, (lane & 16u) | 12u);
        float cN = fmaf(gf, cst, gi * gg);
        float hN = go * ftanh(cN);
        if (sender) {
            cst = cN;
            unsigned dst = la_h + (unsigned)((nxt * HID + (int)rk * 16 + jj) * 4);
#pragma unroll
            for (int r = 0; r < CS; r++)
                st_async_f32(mapa_(dst, (unsigned)r), hN, mapa_(mb_c, (unsigned)r));
        }
        mbar_wait(mb_c, (t >> 1) & 1);

        // heads: warp0 n0/n1 (feedback), warp1 n2..n4 (output only, rk0)
        if (warp == 0) {
            float u0 = 0.0f, u1 = 0.0f;
#pragma unroll
            for (int i = 0; i < 4; i++) {
                float hv = hbuf[nxt][lane + 32 * i];
                u0 = fmaf(hv, woA[i], u0); u1 = fmaf(hv, woB[i], u1);
            }
#pragma unroll
            for (int off = 16; off > 0; off >>= 1) {
                u0 += __shfl_xor_sync(0xffffffffu, u0, off);
                u1 += __shfl_xor_sync(0xffffffffu, u1, off);
            }
            if (lane == 0) {
                float n0 = u0 + bo0, n1 = u1 + bo1;
                pcx += n0; pcy += n1;
                pcs[0] = pcx; pcs[1] = pcy; pcs[2] = n0; pcs[3] = n1;
                if (rk == 0) {
                    out[(size_t)t * 5 + 0] = n0;
                    out[(size_t)t * 5 + 1] = n1;
                }
            }
        } else if (warp == 1 && rk == 0) {
            float u2 = 0.0f, u3 = 0.0f, u4 = 0.0f;
#pragma unroll
            for (int i = 0; i < 4; i++) {
                float hv = hbuf[nxt][lane + 32 * i];
                u2 = fmaf(hv, woA[i], u2); u3 = fmaf(hv, woB[i], u3); u4 = fmaf(hv, woC[i], u4);
            }
#pragma unroll
            for (int off = 16; off > 0; off >>= 1) {
                u2 += __shfl_xor_sync(0xffffffffu, u2, off);
                u3 += __shfl_xor_sync(0xffffffffu, u3, off);
                u4 += __shfl_xor_sync(0xffffffffu, u4, off);
            }
            if (lane == 0) {
                out[(size_t)t * 5 + 2] = u2 + bo2;
                out[(size_t)t * 5 + 3] = u3 + bo3;
                out[(size_t)t * 5 + 4] = u4 + bo4;
            }
        }
        __syncthreads();                                   // pcs visibility
    }
}

// ---------------- Kernel C: phase-1 output head (parallel) ----------------
__global__ void __launch_bounds__(160) olstm_head(
    const float* __restrict__ W_out, const float* __restrict__ b_out,
    float* __restrict__ out)
{
    const int t = blockIdx.x;
    const int tid = threadIdx.x;
    const int j = tid >> 5;
    const unsigned lane = tid & 31;
    const float* h = g_hist + (size_t)t * HID;
    float v = 0.0f;
#pragma unroll
    for (int i = 0; i < 4; i++)
        v = fmaf(h[lane + 32 * i], W_out[j * HID + lane + 32 * i], v);
#pragma unroll
    for (int off = 16; off > 0; off >>= 1)
        v += __shfl_down_sync(0xffffffffu, v, off);
    if (lane == 0) out[(size_t)t * 5 + j] = v + b_out[j];
}

extern "C" void kernel_launch(void* const* d_in, const int* in_sizes, int n_in,
                              void* d_out, int out_size) {
    (void)in_sizes; (void)n_in; (void)out_size;
    const float* observed = (const float*)d_in[0];
    const float* other    = (const float*)d_in[1];
    const float* W_emb    = (const float*)d_in[2];
    const float* b_emb    = (const float*)d_in[3];
    const float* W_ih     = (const float*)d_in[4];
    const float* b_ih     = (const float*)d_in[5];
    const float* W_hh     = (const float*)d_in[6];
    const float* b_hh     = (const float*)d_in[7];
    const float* W_out    = (const float*)d_in[8];
    const float* b_out    = (const float*)d_in[9];
    float* out = (float*)d_out;

    olstm_pre<<<P1, TPB>>>(observed, other, W_emb, b_emb, W_ih);
    olstm_seq<<<CS, TPB>>>(observed, other, W_emb, b_emb, W_ih, b_ih,
                           W_hh, b_hh, W_out, b_out, out);
    olstm_head<<<P1, 160>>>(W_out, b_out, out);
}

// round 5
// speedup vs baseline: 1.3534x; 1.3534x over previous
#include <cuda_runtime.h>
#include <cstdint>

namespace {
constexpr int EMBD  = 64;
constexpr int HID   = 128;
constexpr int NN    = 4096;
constexpr int P1    = 2047;
constexpr int STEPS = 4094;
constexpr int CS    = 8;
constexpr int TPB   = 256;
constexpr int RPC   = 64;           // gate rows per CTA
constexpr int HPC   = 16;           // h indices per CTA
constexpr int NBT   = NN / TPB;     // 16 neighbors per thread

struct SmemB {
    float Wocc[36 * RPC];           // occ weight cols, [b][localrow]
    float xe[EMBD];                 // embedding vector
    float hbuf[2][HID];             // double-buffered h
    float partial[TPB];
    float gact[RPC];
    float bsum[RPC];
    float W_emb_s[EMBD * 2];
    float b_emb_s[EMBD];
    float W_out_s[5 * HID];
    float b_out_s[8];
    float normal_s[8];
    float pc[2], pp[2];
    unsigned wlo[8], whi[8];
    unsigned long long mb[2];       // transaction mbarriers
};
} // namespace

__device__ float g_xih[(size_t)P1 * 512];   // precomputed x@W_ih (permuted)
__device__ float g_hist[(size_t)P1 * HID];  // phase-1 h history

// ---------------- PTX helpers ----------------
__device__ __forceinline__ unsigned ctarank() {
    unsigned r; asm("mov.u32 %0, %%cluster_ctarank;" : "=r"(r)); return r;
}
__device__ __forceinline__ void cluster_sync_() {
    asm volatile("barrier.cluster.arrive.aligned;" ::: "memory");
    asm volatile("barrier.cluster.wait.aligned;" ::: "memory");
}
__device__ __forceinline__ unsigned mapa_(unsigned la, unsigned rank) {
    unsigned ra;
    asm("mapa.shared::cluster.u32 %0, %1, %2;" : "=r"(ra) : "r"(la), "r"(rank));
    return ra;
}
__device__ __forceinline__ void mbar_init(unsigned a, unsigned cnt) {
    asm volatile("mbarrier.init.shared.b64 [%0], %1;" :: "r"(a), "r"(cnt) : "memory");
}
__device__ __forceinline__ void mbar_expect(unsigned a, unsigned bytes) {
    asm volatile("mbarrier.arrive.expect_tx.shared.b64 _, [%0], %1;"
                 :: "r"(a), "r"(bytes) : "memory");
}
__device__ __forceinline__ void mbar_wait(unsigned a, unsigned parity) {
    asm volatile(
        "{\n\t.reg .pred P;\n"
        "WL%=:\n\t"
        "mbarrier.try_wait.parity.acquire.cluster.shared::cta.b64 P, [%0], %1, 0x989680;\n\t"
        "@P bra WD%=;\n\t"
        "bra WL%=;\n"
        "WD%=:\n\t}"
        :: "r"(a), "r"(parity) : "memory");
}
__device__ __forceinline__ void st_async_f32(unsigned raddr, float v, unsigned rmbar) {
    asm volatile(
        "st.async.shared::cluster.mbarrier::complete_tx::bytes.b32 [%0], %1, [%2];"
        :: "r"(raddr), "r"(__float_as_uint(v)), "r"(rmbar) : "memory");
}

// fast activations via MUFU (rel err ~1e-6, far under the 1e-3 threshold)
__device__ __forceinline__ float fsig(float x) {
    return __fdividef(1.0f, 1.0f + __expf(-x));
}
__device__ __forceinline__ float ftanh(float x) {
    return __fdividef(2.0f, 1.0f + __expf(-2.0f * x)) - 1.0f;
}

// occupancy test for one neighbor: exact JAX linspace edge semantics
__device__ __forceinline__ void occ_point(float x, float y, float cx, float cy,
                                          unsigned& lo, unsigned& hi) {
    if (fabsf(x - cx) < 1.6f && fabsf(y - cy) < 1.6f) {
        int ix = -1, iy = -1;
#pragma unroll
        for (int c = 0; c < 6; c++) {
            float ex0 = cx + (0.5f * c - 1.5f);
            float ex1 = cx + (0.5f * c - 1.0f);
            if (x > ex0 && x < ex1) ix = c;
            float ey0 = cy + (0.5f * c - 1.5f);
            float ey1 = cy + (0.5f * c - 1.0f);
            if (y > ey0 && y < ey1) iy = c;
        }
        if (ix >= 0 && iy >= 0) {
            int b = ix * 6 + iy;
            if (b < 32) lo |= 1u << b; else hi |= 1u << (b - 32);
        }
    }
}

// ---------------- Kernel A: phase-1 precompute (fully parallel) ----------------
__global__ void __launch_bounds__(TPB) olstm_pre(
    const float* __restrict__ observed, const float* __restrict__ other,
    const float* __restrict__ W_emb, const float* __restrict__ b_emb,
    const float* __restrict__ W_ih)
{
    __shared__ __align__(16) float x100[100];
    __shared__ unsigned wlo[8], whi[8];
    const int t = blockIdx.x;
    const int tid = threadIdx.x;
    const float px = observed[t * 2],       py = observed[t * 2 + 1];
    const float cx = observed[(t + 1) * 2], cy = observed[(t + 1) * 2 + 1];
    const float dx = cx - px, dy = cy - py;

    const float2* oth2 = reinterpret_cast<const float2*>(other);
    unsigned lo = 0u, hi = 0u;
    for (int i = 0; i < NBT; i++) {
        float2 p = oth2[(size_t)(t + 1) * NN + i * TPB + tid];
        occ_point(p.x, p.y, cx, cy, lo, hi);
    }
    lo = __reduce_or_sync(0xffffffffu, lo);
    hi = __reduce_or_sync(0xffffffffu, hi);
    if ((tid & 31) == 0) { wlo[tid >> 5] = lo; whi[tid >> 5] = hi; }
    if (tid < EMBD) {
        float e = fmaf(dx, W_emb[tid * 2], fmaf(dy, W_emb[tid * 2 + 1], b_emb[tid]));
        x100[tid] = e > 0.0f ? e : 0.0f;
    }
    __syncthreads();
    if (tid >= 64 && tid < 100) {
        int b = tid - 64;
        unsigned fm = (b < 32)
            ? (wlo[0]|wlo[1]|wlo[2]|wlo[3]|wlo[4]|wlo[5]|wlo[6]|wlo[7])
            : (whi[0]|whi[1]|whi[2]|whi[3]|whi[4]|whi[5]|whi[6]|whi[7]);
        x100[tid] = ((fm >> (b & 31)) & 1u) ? 1.0f : 0.0f;
    }
    __syncthreads();

    const float4* xq = reinterpret_cast<const float4*>(x100);
    const float4* w0 = reinterpret_cast<const float4*>(W_ih + (size_t)tid * 100);
    const float4* w1 = reinterpret_cast<const float4*>(W_ih + (size_t)(tid + 256) * 100);
    float a0 = 0.0f, a1 = 0.0f;
#pragma unroll
    for (int i = 0; i < 25; i++) {
        float4 xx = xq[i], wa = w0[i], wb = w1[i];
        a0 = fmaf(wa.x, xx.x, a0); a0 = fmaf(wa.y, xx.y, a0);
        a0 = fmaf(wa.z, xx.z, a0); a0 = fmaf(wa.w, xx.w, a0);
        a1 = fmaf(wb.x, xx.x, a1); a1 = fmaf(wb.y, xx.y, a1);
        a1 = fmaf(wb.z, xx.z, a1); a1 = fmaf(wb.w, xx.w, a1);
    }
    // permute: idx = rk*64 + q*16 + jj for gate row gr = q*128 + rk*16 + jj
    const int r0 = tid, r1 = tid + 256;
    g_xih[(size_t)t * 512 + ((r0 >> 4) & 7) * 64 + (r0 >> 7) * 16 + (r0 & 15)] = a0;
    g_xih[(size_t)t * 512 + ((r1 >> 4) & 7) * 64 + (r1 >> 7) * 16 + (r1 & 15)] = a1;
}

// ---------------- Kernel B helpers ----------------
__device__ __forceinline__ void gates_and_send(SmemB* s, int tid, unsigned rk,
                                               int nxt, unsigned mb_c, unsigned la_h,
                                               float& cst, float* hist) {
    if (tid < 64) {
        float gv = s->bsum[tid] + s->partial[tid] + s->partial[tid + 64]
                 + s->partial[tid + 128] + s->partial[tid + 192];
        float av = (tid < 32 || tid >= 48) ? fsig(gv) : ftanh(gv);
        s->gact[tid] = av;
        asm volatile("bar.sync 1, 64;" ::: "memory");
        if (tid < 16) {
            float ig = s->gact[tid],      fg = s->gact[16 + tid];
            float gg = s->gact[32 + tid], og = s->gact[48 + tid];
            float cN = fmaf(fg, cst, ig * gg);
            cst = cN;
            float hN = og * ftanh(cN);
            unsigned dst = la_h + (unsigned)((nxt * HID + (int)rk * HPC + tid) * 4);
#pragma unroll
            for (int r = 0; r < CS; r++)
                st_async_f32(mapa_(dst, (unsigned)r), hN, mapa_(mb_c, (unsigned)r));
            if (hist) hist[rk * HPC + tid] = hN;  // off critical path
        }
    }
}

__device__ __forceinline__ void head_pos(SmemB* s, int tid, const float* hn,
                                         float bx, float by) {
    if (tid < 32) {
        float v0 = 0.0f, v1 = 0.0f;
#pragma unroll
        for (int i = 0; i < 4; i++) {
            float hv = hn[tid + 32 * i];
            v0 = fmaf(hv, s->W_out_s[tid + 32 * i], v0);
            v1 = fmaf(hv, s->W_out_s[HID + tid + 32 * i], v1);
        }
#pragma unroll
        for (int o = 16; o > 0; o >>= 1) {
            v0 += __shfl_down_sync(0xffffffffu, v0, o);
            v1 += __shfl_down_sync(0xffffffffu, v1, o);
        }
        if (tid == 0) {
            float n0 = v0 + s->b_out_s[0], n1 = v1 + s->b_out_s[1];
            s->normal_s[0] = n0; s->normal_s[1] = n1;
            s->pp[0] = s->pc[0]; s->pp[1] = s->pc[1];
            s->pc[0] = bx + n0;  s->pc[1] = by + n1;
        }
    } else if (tid < 128) {
        int j = (tid >> 5) + 1, ln = tid & 31;
        const float* wo = s->W_out_s + j * HID;
        float v = 0.0f;
#pragma unroll
        for (int i = 0; i < 4; i++) v = fmaf(hn[ln + 32 * i], wo[ln + 32 * i], v);
#pragma unroll
        for (int o = 16; o > 0; o >>= 1) v += __shfl_down_sync(0xffffffffu, v, o);
        if (ln == 0) s->normal_s[j] = v + s->b_out_s[j];
    }
}

// ---------------- Kernel B: sequential cluster (8 CTA x 256) ----------------
__global__ void __cluster_dims__(CS, 1, 1) __launch_bounds__(TPB, 1)
olstm_seq(const float* __restrict__ observed, const float* __restrict__ other,
          const float* __restrict__ W_emb, const float* __restrict__ b_emb,
          const float* __restrict__ W_ih,  const float* __restrict__ b_ih,
          const float* __restrict__ W_hh,  const float* __restrict__ b_hh,
          const float* __restrict__ W_out, const float* __restrict__ b_out,
          float* __restrict__ out)
{
    __shared__ __align__(16) SmemB s;
    const int tid = threadIdx.x;
    const unsigned lane = tid & 31;
    const int warp = tid >> 5;
    const unsigned rk = ctarank();
    const int m = tid & 63, part = tid >> 6;
    const int gr = (m >> 4) * HID + (int)rk * HPC + (m & 15);

    // register-resident gate weights: 16 emb cols + 32 h cols per thread
    float w[48];
#pragma unroll
    for (int i = 0; i < 16; i++) w[i] = W_ih[(size_t)gr * 100 + part * 16 + i];
#pragma unroll
    for (int i = 0; i < 32; i++) w[16 + i] = W_hh[(size_t)gr * 128 + part * 32 + i];

    for (int idx = tid; idx < 36 * RPC; idx += TPB) {
        int b = idx >> 6, mm = idx & 63;
        int g2 = (mm >> 4) * HID + (int)rk * HPC + (mm & 15);
        s.Wocc[idx] = W_ih[(size_t)g2 * 100 + 64 + b];
    }
    if (tid < RPC) s.bsum[tid] = b_ih[gr] + b_hh[gr];
    for (int i = tid; i < EMBD * 2; i += TPB) s.W_emb_s[i] = W_emb[i];
    if (tid < EMBD) s.b_emb_s[tid] = b_emb[tid];
    for (int i = tid; i < 5 * HID; i += TPB) s.W_out_s[i] = W_out[i];
    if (tid < 5) s.b_out_s[tid] = b_out[tid];
    for (int i = tid; i < HID; i += TPB) { s.hbuf[0][i] = 0.0f; s.hbuf[1][i] = 0.0f; }

    const unsigned mb0  = (unsigned)__cvta_generic_to_shared(&s.mb[0]);
    const unsigned mb1  = mb0 + 8;
    const unsigned la_h = (unsigned)__cvta_generic_to_shared(&s.hbuf[0][0]);
    if (tid == 0) { mbar_init(mb0, 1); mbar_init(mb1, 1); mbar_expect(mb0, 512); }
    __syncthreads();
    cluster_sync_();

    const float2* oth2 = reinterpret_cast<const float2*>(other);
    float2 nb[NBT];
    float cst = 0.0f;                                  // cell state (tid<16)
    float pcx = 0.0f, pcy = 0.0f, ppx = 0.0f, ppy = 0.0f;  // tid0
    float xcur = 0.0f, xnext = 0.0f;
    if (tid < 64) xcur = g_xih[(size_t)rk * 64 + tid];

    // ============ phase 1: precomputed x, no head, no trailing sync ============
    for (int t = 0; t < P1; t++) {
        const int cur = t & 1, nxt = cur ^ 1;
        const unsigned mb_c = (t & 1) ? mb1 : mb0;
        const unsigned mb_n = (t & 1) ? mb0 : mb1;
        if (tid == 0) mbar_expect(mb_n, 512);
        if (tid < 64 && t + 1 < P1)
            xnext = g_xih[(size_t)(t + 1) * 512 + (size_t)rk * 64 + tid];

        const float4* hq = reinterpret_cast<const float4*>(s.hbuf[cur] + part * 32);
        float a0 = (part == 0) ? xcur : 0.0f, a1 = 0.0f, a2 = 0.0f, a3 = 0.0f;
#pragma unroll
        for (int i = 0; i < 8; i++) {
            float4 hh = hq[i];
            a0 = fmaf(w[16 + 4 * i], hh.x, a0); a1 = fmaf(w[17 + 4 * i], hh.y, a1);
            a2 = fmaf(w[18 + 4 * i], hh.z, a2); a3 = fmaf(w[19 + 4 * i], hh.w, a3);
        }
        s.partial[tid] = (a0 + a1) + (a2 + a3);
        if (t == P1 - 1) {
#pragma unroll
            for (int i = 0; i < NBT; i++)
                nb[i] = oth2[(size_t)(P1 + 1) * NN + i * TPB + tid];
        }
        __syncthreads();
        gates_and_send(&s, tid, rk, nxt, mb_c, la_h, cst, g_hist + (size_t)t * HID);
        mbar_wait(mb_c, (t >> 1) & 1);
        // last two steps only: positions for the phase-2 carry
        if (t >= P1 - 2 && warp == 0) {
            float u0 = 0.0f, u1 = 0.0f;
#pragma unroll
            for (int i = 0; i < 4; i++) {
                float hv = s.hbuf[nxt][lane + 32 * i];
                u0 = fmaf(hv, s.W_out_s[lane + 32 * i], u0);
                u1 = fmaf(hv, s.W_out_s[HID + lane + 32 * i], u1);
            }
#pragma unroll
            for (int o = 16; o > 0; o >>= 1) {
                u0 += __shfl_xor_sync(0xffffffffu, u0, o);
                u1 += __shfl_xor_sync(0xffffffffu, u1, o);
            }
            if (lane == 0) {
                ppx = pcx; ppy = pcy;
                pcx = observed[(t + 1) * 2]     + u0 + s.b_out_s[0];
                pcy = observed[(t + 1) * 2 + 1] + u1 + s.b_out_s[1];
            }
        }
        xcur = xnext;
    }

    if (tid == 0) { s.pc[0] = pcx; s.pc[1] = pcy; s.pp[0] = ppx; s.pp[1] = ppy; }
    __syncthreads();

    // ======================= phase 2 (feedback) =======================
    for (int t = P1; t < STEPS; t++) {
        const int cur = t & 1, nxt = cur ^ 1;
        const unsigned mb_c = (t & 1) ? mb1 : mb0;
        const unsigned mb_n = (t & 1) ? mb0 : mb1;
        if (tid == 0) mbar_expect(mb_n, 512);

        const float cx = s.pc[0], cy = s.pc[1];
        const float dx = cx - s.pp[0], dy = cy - s.pp[1];
        unsigned lo = 0u, hi = 0u;
#pragma unroll
        for (int i = 0; i < NBT; i++) occ_point(nb[i].x, nb[i].y, cx, cy, lo, hi);
        lo = __reduce_or_sync(0xffffffffu, lo);
        hi = __reduce_or_sync(0xffffffffu, hi);
        if (lane == 0) { s.wlo[warp] = lo; s.whi[warp] = hi; }
        if (tid < 64) {
            float e = fmaf(dx, s.W_emb_s[tid * 2],
                      fmaf(dy, s.W_emb_s[tid * 2 + 1], s.b_emb_s[tid]));
            s.xe[tid] = e > 0.0f ? e : 0.0f;
        }
        __syncthreads();

        const float4* hq = reinterpret_cast<const float4*>(s.hbuf[cur] + part * 32);
        const float4* eq = reinterpret_cast<const float4*>(s.xe + part * 16);
        float a0 = 0.0f, a1 = 0.0f, a2 = 0.0f, a3 = 0.0f;
#pragma unroll
        for (int i = 0; i < 4; i++) {
            float4 xx = eq[i];
            a0 = fmaf(w[4 * i],     xx.x, a0); a1 = fmaf(w[4 * i + 1], xx.y, a1);
            a2 = fmaf(w[4 * i + 2], xx.z, a2); a3 = fmaf(w[4 * i + 3], xx.w, a3);
        }
#pragma unroll
        for (int i = 0; i < 8; i++) {
            float4 hh = hq[i];
            a0 = fmaf(w[16 + 4 * i], hh.x, a0); a1 = fmaf(w[17 + 4 * i], hh.y, a1);
            a2 = fmaf(w[18 + 4 * i], hh.z, a2); a3 = fmaf(w[19 + 4 * i], hh.w, a3);
        }
        float acc = (a0 + a1) + (a2 + a3);
        if (part == 0) {
            unsigned flo = s.wlo[0]|s.wlo[1]|s.wlo[2]|s.wlo[3]|s.wlo[4]|s.wlo[5]|s.wlo[6]|s.wlo[7];
            unsigned fhi = s.whi[0]|s.whi[1]|s.whi[2]|s.whi[3]|s.whi[4]|s.whi[5]|s.whi[6]|s.whi[7];
            while (flo) { int b = __ffs(flo) - 1; flo &= flo - 1; acc += s.Wocc[b * RPC + m]; }
            while (fhi) { int b = __ffs(fhi) - 1; fhi &= fhi - 1; acc += s.Wocc[(b + 32) * RPC + m]; }
        }
        s.partial[tid] = acc;
        if (t + 1 < STEPS) {
#pragma unroll
            for (int i = 0; i < NBT; i++)
                nb[i] = oth2[(size_t)(t + 2) * NN + i * TPB + tid];
        }
        __syncthreads();
        gates_and_send(&s, tid, rk, nxt, mb_c, la_h, cst, nullptr);
        mbar_wait(mb_c, (t >> 1) & 1);
        head_pos(&s, tid, s.hbuf[nxt], cx, cy);
        __syncthreads();
        if (rk == 0 && tid < 5) out[(size_t)t * 5 + tid] = s.normal_s[tid];
    }
}

// ---------------- Kernel C: phase-1 output head (parallel) ----------------
__global__ void __launch_bounds__(160) olstm_head(
    const float* __restrict__ W_out, const float* __restrict__ b_out,
    float* __restrict__ out)
{
    const int t = blockIdx.x;
    const int tid = threadIdx.x;
    const int j = tid >> 5;
    const unsigned lane = tid & 31;
    const float* h = g_hist + (size_t)t * HID;
    float v = 0.0f;
#pragma unroll
    for (int i = 0; i < 4; i++)
        v = fmaf(h[lane + 32 * i], W_out[j * HID + lane + 32 * i], v);
#pragma unroll
    for (int off = 16; off > 0; off >>= 1)
        v += __shfl_down_sync(0xffffffffu, v, off);
    if (lane == 0) out[(size_t)t * 5 + j] = v + b_out[j];
}

extern "C" void kernel_launch(void* const* d_in, const int* in_sizes, int n_in,
                              void* d_out, int out_size) {
    (void)in_sizes; (void)n_in; (void)out_size;
    const float* observed = (const float*)d_in[0];
    const float* other    = (const float*)d_in[1];
    const float* W_emb    = (const float*)d_in[2];
    const float* b_emb    = (const float*)d_in[3];
    const float* W_ih     = (const float*)d_in[4];
    const float* b_ih     = (const float*)d_in[5];
    const float* W_hh     = (const float*)d_in[6];
    const float* b_hh     = (const float*)d_in[7];
    const float* W_out    = (const float*)d_in[8];
    const float* b_out    = (const float*)d_in[9];
    float* out = (float*)d_out;

    olstm_pre<<<P1, TPB>>>(observed, other, W_emb, b_emb, W_ih);
    olstm_seq<<<CS, TPB>>>(observed, other, W_emb, b_emb, W_ih, b_ih,
                           W_hh, b_hh, W_out, b_out, out);
    olstm_head<<<P1, 160>>>(W_out, b_out, out);
}

// round 6
// speedup vs baseline: 1.4308x; 1.0572x over previous
#include <cuda_runtime.h>
#include <cstdint>

namespace {
constexpr int EMBD  = 64;
constexpr int HID   = 128;
constexpr int NN    = 4096;
constexpr int P1    = 2047;
constexpr int STEPS = 4094;
constexpr int CS    = 8;
constexpr int TPB   = 256;
constexpr int RPC   = 64;           // gate rows per CTA
constexpr int HPC   = 16;           // h indices per CTA
constexpr int NBT   = NN / TPB;     // 16 neighbors per thread

struct SmemB {
    float xe[EMBD];                 // embedding vector
    float hbuf[2][HID];             // double-buffered h
    float partial[TPB];
    float gact[RPC];
    float bsum[RPC];
    float W_emb_s[EMBD * 2];
    float b_emb_s[EMBD];
    float W_out_s[5 * HID];
    float b_out_s[8];
    float pc[2], pp[2];
    unsigned wm[16];                // [0..7]=lo words per warp, [8..15]=hi
    unsigned long long mb[2];       // transaction mbarriers
};
} // namespace

__device__ float g_xih[(size_t)P1 * 512];      // precomputed x@W_ih (permuted)
__device__ float g_hist[(size_t)STEPS * HID];  // h history (both phases)

// ---------------- PTX helpers ----------------
__device__ __forceinline__ unsigned ctarank() {
    unsigned r; asm("mov.u32 %0, %%cluster_ctarank;" : "=r"(r)); return r;
}
__device__ __forceinline__ void cluster_sync_() {
    asm volatile("barrier.cluster.arrive.aligned;" ::: "memory");
    asm volatile("barrier.cluster.wait.aligned;" ::: "memory");
}
__device__ __forceinline__ unsigned mapa_(unsigned la, unsigned rank) {
    unsigned ra;
    asm("mapa.shared::cluster.u32 %0, %1, %2;" : "=r"(ra) : "r"(la), "r"(rank));
    return ra;
}
__device__ __forceinline__ void mbar_init(unsigned a, unsigned cnt) {
    asm volatile("mbarrier.init.shared.b64 [%0], %1;" :: "r"(a), "r"(cnt) : "memory");
}
__device__ __forceinline__ void mbar_expect(unsigned a, unsigned bytes) {
    asm volatile("mbarrier.arrive.expect_tx.shared.b64 _, [%0], %1;"
                 :: "r"(a), "r"(bytes) : "memory");
}
__device__ __forceinline__ void mbar_wait(unsigned a, unsigned parity) {
    asm volatile(
        "{\n\t.reg .pred P;\n"
        "WL%=:\n\t"
        "mbarrier.try_wait.parity.acquire.cluster.shared::cta.b64 P, [%0], %1, 0x989680;\n\t"
        "@P bra WD%=;\n\t"
        "bra WL%=;\n"
        "WD%=:\n\t}"
        :: "r"(a), "r"(parity) : "memory");
}
__device__ __forceinline__ void st_async_f32(unsigned raddr, float v, unsigned rmbar) {
    asm volatile(
        "st.async.shared::cluster.mbarrier::complete_tx::bytes.b32 [%0], %1, [%2];"
        :: "r"(raddr), "r"(__float_as_uint(v)), "r"(rmbar) : "memory");
}

// fast activations via MUFU (rel err ~1e-6, far under the 1e-3 threshold)
__device__ __forceinline__ float fsig(float x) {
    return __fdividef(1.0f, 1.0f + __expf(-x));
}
__device__ __forceinline__ float ftanh(float x) {
    return __fdividef(2.0f, 1.0f + __expf(-2.0f * x)) - 1.0f;
}

// occupancy test for one neighbor: exact JAX linspace edge semantics
__device__ __forceinline__ void occ_point(float x, float y, float cx, float cy,
                                          unsigned& lo, unsigned& hi) {
    if (fabsf(x - cx) < 1.6f && fabsf(y - cy) < 1.6f) {
        int ix = -1, iy = -1;
#pragma unroll
        for (int c = 0; c < 6; c++) {
            float ex0 = cx + (0.5f * c - 1.5f);
            float ex1 = cx + (0.5f * c - 1.0f);
            if (x > ex0 && x < ex1) ix = c;
            float ey0 = cy + (0.5f * c - 1.5f);
            float ey1 = cy + (0.5f * c - 1.0f);
            if (y > ey0 && y < ey1) iy = c;
        }
        if (ix >= 0 && iy >= 0) {
            int b = ix * 6 + iy;
            if (b < 32) lo |= 1u << b; else hi |= 1u << (b - 32);
        }
    }
}

// ---------------- Kernel A: phase-1 precompute (fully parallel) ----------------
__global__ void __launch_bounds__(TPB) olstm_pre(
    const float* __restrict__ observed, const float* __restrict__ other,
    const float* __restrict__ W_emb, const float* __restrict__ b_emb,
    const float* __restrict__ W_ih)
{
    __shared__ __align__(16) float x100[100];
    __shared__ unsigned wlo[8], whi[8];
    const int t = blockIdx.x;
    const int tid = threadIdx.x;
    const float px = observed[t * 2],       py = observed[t * 2 + 1];
    const float cx = observed[(t + 1) * 2], cy = observed[(t + 1) * 2 + 1];
    const float dx = cx - px, dy = cy - py;

    const float2* oth2 = reinterpret_cast<const float2*>(other);
    unsigned lo = 0u, hi = 0u;
    for (int i = 0; i < NBT; i++) {
        float2 p = oth2[(size_t)(t + 1) * NN + i * TPB + tid];
        occ_point(p.x, p.y, cx, cy, lo, hi);
    }
    lo = __reduce_or_sync(0xffffffffu, lo);
    hi = __reduce_or_sync(0xffffffffu, hi);
    if ((tid & 31) == 0) { wlo[tid >> 5] = lo; whi[tid >> 5] = hi; }
    if (tid < EMBD) {
        float e = fmaf(dx, W_emb[tid * 2], fmaf(dy, W_emb[tid * 2 + 1], b_emb[tid]));
        x100[tid] = e > 0.0f ? e : 0.0f;
    }
    __syncthreads();
    if (tid >= 64 && tid < 100) {
        int b = tid - 64;
        unsigned fm = (b < 32)
            ? (wlo[0]|wlo[1]|wlo[2]|wlo[3]|wlo[4]|wlo[5]|wlo[6]|wlo[7])
            : (whi[0]|whi[1]|whi[2]|whi[3]|whi[4]|whi[5]|whi[6]|whi[7]);
        x100[tid] = ((fm >> (b & 31)) & 1u) ? 1.0f : 0.0f;
    }
    __syncthreads();

    const float4* xq = reinterpret_cast<const float4*>(x100);
    const float4* w0 = reinterpret_cast<const float4*>(W_ih + (size_t)tid * 100);
    const float4* w1 = reinterpret_cast<const float4*>(W_ih + (size_t)(tid + 256) * 100);
    float a0 = 0.0f, a1 = 0.0f;
#pragma unroll
    for (int i = 0; i < 25; i++) {
        float4 xx = xq[i], wa = w0[i], wb = w1[i];
        a0 = fmaf(wa.x, xx.x, a0); a0 = fmaf(wa.y, xx.y, a0);
        a0 = fmaf(wa.z, xx.z, a0); a0 = fmaf(wa.w, xx.w, a0);
        a1 = fmaf(wb.x, xx.x, a1); a1 = fmaf(wb.y, xx.y, a1);
        a1 = fmaf(wb.z, xx.z, a1); a1 = fmaf(wb.w, xx.w, a1);
    }
    // permute: idx = rk*64 + q*16 + jj for gate row gr = q*128 + rk*16 + jj
    const int r0 = tid, r1 = tid + 256;
    g_xih[(size_t)t * 512 + ((r0 >> 4) & 7) * 64 + (r0 >> 7) * 16 + (r0 & 15)] = a0;
    g_xih[(size_t)t * 512 + ((r1 >> 4) & 7) * 64 + (r1 >> 7) * 16 + (r1 & 15)] = a1;
}

// ---------------- Kernel B helpers ----------------
// 128-thread fanout: thread (j = tid&15, r = tid>>4) sends h[j] to rank r.
// Cell state cst is replicated across the 8 rank-groups (identical updates).
__device__ __forceinline__ void gates_and_send(SmemB* s, int tid, unsigned rk,
                                               int nxt, unsigned mb_c, unsigned la_h,
                                               float& cst, float* hist) {
    if (tid < 128) {
        if (tid < 64) {
            float gv = s->bsum[tid] + s->partial[tid] + s->partial[tid + 64]
                     + s->partial[tid + 128] + s->partial[tid + 192];
            s->gact[tid] = (tid < 32 || tid >= 48) ? fsig(gv) : ftanh(gv);
        }
        asm volatile("bar.sync 1, 128;" ::: "memory");
        const int j = tid & 15, r = tid >> 4;
        float ig = s->gact[j],      fg = s->gact[16 + j];
        float gg = s->gact[32 + j], og = s->gact[48 + j];
        float cN = fmaf(fg, cst, ig * gg);
        cst = cN;
        float hN = og * ftanh(cN);
        unsigned dst = la_h + (unsigned)((nxt * HID + (int)rk * HPC + j) * 4);
        st_async_f32(mapa_(dst, (unsigned)r), hN, mapa_(mb_c, (unsigned)r));
        if (r == 0) hist[rk * HPC + j] = hN;   // off critical path (STG)
    }
}

// ---------------- Kernel B: sequential cluster (8 CTA x 256) ----------------
__global__ void __cluster_dims__(CS, 1, 1) __launch_bounds__(TPB, 1)
olstm_seq(const float* __restrict__ observed, const float* __restrict__ other,
          const float* __restrict__ W_emb, const float* __restrict__ b_emb,
          const float* __restrict__ W_ih,  const float* __restrict__ b_ih,
          const float* __restrict__ W_hh,  const float* __restrict__ b_hh,
          const float* __restrict__ W_out, const float* __restrict__ b_out,
          float* __restrict__ out)
{
    __shared__ __align__(16) SmemB s;
    const int tid = threadIdx.x;
    const unsigned lane = tid & 31;
    const int warp = tid >> 5;
    const unsigned rk = ctarank();
    const int m = tid & 63, part = tid >> 6;
    const int gr = (m >> 4) * HID + (int)rk * HPC + (m & 15);

    // register-resident gate weights: 16 emb cols + 32 h cols + 9 occ cols
    float w[48], wocc[9];
#pragma unroll
    for (int i = 0; i < 16; i++) w[i] = W_ih[(size_t)gr * 100 + part * 16 + i];
#pragma unroll
    for (int i = 0; i < 32; i++) w[16 + i] = W_hh[(size_t)gr * 128 + part * 32 + i];
#pragma unroll
    for (int i = 0; i < 9; i++)  wocc[i] = W_ih[(size_t)gr * 100 + 64 + part * 9 + i];

    if (tid < RPC) s.bsum[tid] = b_ih[gr] + b_hh[gr];
    for (int i = tid; i < EMBD * 2; i += TPB) s.W_emb_s[i] = W_emb[i];
    if (tid < EMBD) s.b_emb_s[tid] = b_emb[tid];
    for (int i = tid; i < 5 * HID; i += TPB) s.W_out_s[i] = W_out[i];
    if (tid < 5) s.b_out_s[tid] = b_out[tid];
    for (int i = tid; i < HID; i += TPB) { s.hbuf[0][i] = 0.0f; s.hbuf[1][i] = 0.0f; }

    const unsigned mb0  = (unsigned)__cvta_generic_to_shared(&s.mb[0]);
    const unsigned mb1  = mb0 + 8;
    const unsigned la_h = (unsigned)__cvta_generic_to_shared(&s.hbuf[0][0]);
    if (tid == 0) { mbar_init(mb0, 1); mbar_init(mb1, 1); mbar_expect(mb0, 512); }
    __syncthreads();
    cluster_sync_();

    const float2* oth2 = reinterpret_cast<const float2*>(other);
    float2 nb[NBT];
    float cst = 0.0f;                                  // replicated cell state
    float pcx = 0.0f, pcy = 0.0f, ppx = 0.0f, ppy = 0.0f;  // tid0 scalars
    float xcur = 0.0f, xnext = 0.0f;
    if (tid < 64) xcur = g_xih[(size_t)rk * 64 + tid];

    // ============ phase 1: precomputed x, no head, no trailing sync ============
    for (int t = 0; t < P1; t++) {
        const int cur = t & 1, nxt = cur ^ 1;
        const unsigned mb_c = (t & 1) ? mb1 : mb0;
        const unsigned mb_n = (t & 1) ? mb0 : mb1;
        if (tid == 0) mbar_expect(mb_n, 512);
        if (tid < 64 && t + 1 < P1)
            xnext = g_xih[(size_t)(t + 1) * 512 + (size_t)rk * 64 + tid];

        const float4* hq = reinterpret_cast<const float4*>(s.hbuf[cur] + part * 32);
        float a0 = (part == 0) ? xcur : 0.0f, a1 = 0.0f, a2 = 0.0f, a3 = 0.0f;
#pragma unroll
        for (int i = 0; i < 8; i++) {
            float4 hh = hq[i];
            a0 = fmaf(w[16 + 4 * i], hh.x, a0); a1 = fmaf(w[17 + 4 * i], hh.y, a1);
            a2 = fmaf(w[18 + 4 * i], hh.z, a2); a3 = fmaf(w[19 + 4 * i], hh.w, a3);
        }
        s.partial[tid] = (a0 + a1) + (a2 + a3);
        if (t == P1 - 1) {
#pragma unroll
            for (int i = 0; i < NBT; i++)
                nb[i] = oth2[(size_t)(P1 + 1) * NN + i * TPB + tid];
        }
        __syncthreads();
        gates_and_send(&s, tid, rk, nxt, mb_c, la_h, cst, g_hist + (size_t)t * HID);
        mbar_wait(mb_c, (t >> 1) & 1);
        // last two steps only: positions for the phase-2 carry
        if (t >= P1 - 2 && warp == 0) {
            float u0 = 0.0f, u1 = 0.0f;
#pragma unroll
            for (int i = 0; i < 4; i++) {
                float hv = s.hbuf[nxt][lane + 32 * i];
                u0 = fmaf(hv, s.W_out_s[lane + 32 * i], u0);
                u1 = fmaf(hv, s.W_out_s[HID + lane + 32 * i], u1);
            }
#pragma unroll
            for (int o = 16; o > 0; o >>= 1) {
                u0 += __shfl_xor_sync(0xffffffffu, u0, o);
                u1 += __shfl_xor_sync(0xffffffffu, u1, o);
            }
            if (lane == 0) {
                ppx = pcx; ppy = pcy;
                pcx = observed[(t + 1) * 2]     + u0 + s.b_out_s[0];
                pcy = observed[(t + 1) * 2 + 1] + u1 + s.b_out_s[1];
            }
        }
        xcur = xnext;
    }

    if (tid == 0) { s.pc[0] = pcx; s.pc[1] = pcy; s.pp[0] = ppx; s.pp[1] = ppy; }
    __syncthreads();

    // ======================= phase 2 (feedback) =======================
    for (int t = P1; t < STEPS; t++) {
        const int cur = t & 1, nxt = cur ^ 1;
        const unsigned mb_c = (t & 1) ? mb1 : mb0;
        const unsigned mb_n = (t & 1) ? mb0 : mb1;
        if (tid == 0) mbar_expect(mb_n, 512);

        const float cx = s.pc[0], cy = s.pc[1];
        const float dx = cx - s.pp[0], dy = cy - s.pp[1];
        unsigned lo = 0u, hi = 0u;
#pragma unroll
        for (int i = 0; i < NBT; i++) occ_point(nb[i].x, nb[i].y, cx, cy, lo, hi);
        lo = __reduce_or_sync(0xffffffffu, lo);
        hi = __reduce_or_sync(0xffffffffu, hi);
        if (lane == 0) { s.wm[warp] = lo; s.wm[8 + warp] = hi; }
        if (tid < 64) {
            float e = fmaf(dx, s.W_emb_s[tid * 2],
                      fmaf(dy, s.W_emb_s[tid * 2 + 1], s.b_emb_s[tid]));
            s.xe[tid] = e > 0.0f ? e : 0.0f;
        }
        __syncthreads();

        // GEMV: emb (reg weights x SMEM xe) + h + occ (reg weights x bits)
        const float4* hq = reinterpret_cast<const float4*>(s.hbuf[cur] + part * 32);
        const float4* eq = reinterpret_cast<const float4*>(s.xe + part * 16);
        float a0 = 0.0f, a1 = 0.0f, a2 = 0.0f, a3 = 0.0f;
#pragma unroll
        for (int i = 0; i < 4; i++) {
            float4 xx = eq[i];
            a0 = fmaf(w[4 * i],     xx.x, a0); a1 = fmaf(w[4 * i + 1], xx.y, a1);
            a2 = fmaf(w[4 * i + 2], xx.z, a2); a3 = fmaf(w[4 * i + 3], xx.w, a3);
        }
#pragma unroll
        for (int i = 0; i < 8; i++) {
            float4 hh = hq[i];
            a0 = fmaf(w[16 + 4 * i], hh.x, a0); a1 = fmaf(w[17 + 4 * i], hh.y, a1);
            a2 = fmaf(w[18 + 4 * i], hh.z, a2); a3 = fmaf(w[19 + 4 * i], hh.w, a3);
        }
        {
            const uint4* wmv = reinterpret_cast<const uint4*>(s.wm);
            uint4 A = wmv[0], B = wmv[1], C = wmv[2], D = wmv[3];
            unsigned flo = A.x|A.y|A.z|A.w|B.x|B.y|B.z|B.w;
            unsigned fhi = C.x|C.y|C.z|C.w|D.x|D.y|D.z|D.w;
            unsigned long long occm = (((unsigned long long)fhi << 32) | flo) >> (part * 9);
#pragma unroll
            for (int i = 0; i < 9; i++) {
                float xb = ((occm >> i) & 1ull) ? 1.0f : 0.0f;
                a0 = fmaf(wocc[i], xb, a0);
            }
        }
        s.partial[tid] = (a0 + a1) + (a2 + a3);
        if (t + 1 < STEPS) {
#pragma unroll
            for (int i = 0; i < NBT; i++)
                nb[i] = oth2[(size_t)(t + 2) * NN + i * TPB + tid];
        }
        __syncthreads();
        gates_and_send(&s, tid, rk, nxt, mb_c, la_h, cst, g_hist + (size_t)t * HID);
        mbar_wait(mb_c, (t >> 1) & 1);

        // post-wait head: n0/n1 only (n2..4 done by kernel C from g_hist)
        if (warp == 0) {
            float u0 = 0.0f, u1 = 0.0f;
#pragma unroll
            for (int i = 0; i < 4; i++) {
                float hv = s.hbuf[nxt][lane + 32 * i];
                u0 = fmaf(hv, s.W_out_s[lane + 32 * i], u0);
                u1 = fmaf(hv, s.W_out_s[HID + lane + 32 * i], u1);
            }
#pragma unroll
            for (int o = 16; o > 0; o >>= 1) {
                u0 += __shfl_xor_sync(0xffffffffu, u0, o);
                u1 += __shfl_xor_sync(0xffffffffu, u1, o);
            }
            if (lane == 0) {
                float n0 = u0 + s.b_out_s[0], n1 = u1 + s.b_out_s[1];
                s.pp[0] = s.pc[0]; s.pp[1] = s.pc[1];
                s.pc[0] = s.pc[0] + n0; s.pc[1] = s.pc[1] + n1;
                if (rk == 0) {
                    out[(size_t)t * 5 + 0] = n0;
                    out[(size_t)t * 5 + 1] = n1;
                }
            }
        }
        __syncthreads();                               // pc/pp visibility
    }
}

// ---------------- Kernel C: output heads (parallel) ----------------
// t < P1: all 5 outputs.  t >= P1: outputs 2..4 (0,1 written by olstm_seq).
__global__ void __launch_bounds__(160) olstm_head(
    const float* __restrict__ W_out, const float* __restrict__ b_out,
    float* __restrict__ out)
{
    const int t = blockIdx.x;
    const int tid = threadIdx.x;
    const int j = tid >> 5;
    const unsigned lane = tid & 31;
    if (t >= P1 && j < 2) return;
    const float* h = g_hist + (size_t)t * HID;
    float v = 0.0f;
#pragma unroll
    for (int i = 0; i < 4; i++)
        v = fmaf(h[lane + 32 * i], W_out[j * HID + lane + 32 * i], v);
#pragma unroll
    for (int off = 16; off > 0; off >>= 1)
        v += __shfl_down_sync(0xffffffffu, v, off);
    if (lane == 0) out[(size_t)t * 5 + j] = v + b_out[j];
}

extern "C" void kernel_launch(void* const* d_in, const int* in_sizes, int n_in,
                              void* d_out, int out_size) {
    (void)in_sizes; (void)n_in; (void)out_size;
    const float* observed = (const float*)d_in[0];
    const float* other    = (const float*)d_in[1];
    const float* W_emb    = (const float*)d_in[2];
    const float* b_emb    = (const float*)d_in[3];
    const float* W_ih     = (const float*)d_in[4];
    const float* b_ih     = (const float*)d_in[5];
    const float* W_hh     = (const float*)d_in[6];
    const float* b_hh     = (const float*)d_in[7];
    const float* W_out    = (const float*)d_in[8];
    const float* b_out    = (const float*)d_in[9];
    float* out = (float*)d_out;

    olstm_pre<<<P1, TPB>>>(observed, other, W_emb, b_emb, W_ih);
    olstm_seq<<<CS, TPB>>>(observed, other, W_emb, b_emb, W_ih, b_ih,
                           W_hh, b_hh, W_out, b_out, out);
    olstm_head<<<STEPS, 160>>>(W_out, b_out, out);
}